// round 1
// baseline (speedup 1.0000x reference)
#include <cuda_runtime.h>

// Heirachical_Loss: loss = sum_i (1 - win_i)
// win_i = 0.5*S_all(i) + 0.25*S100(i, t/100) + 0.125*S10(i, t/10) + 0.125*x[i,t]
// B=32768 rows, C=1000 classes. Pure streaming reduction, HBM-bound.

#define NROWS 32768
#define NCOLS 1000
#define F4_PER_ROW 250          // 1000 floats = 250 float4 (row stride 4000 B, 16B aligned)
#define ROWS_PER_BLOCK 8
#define NBLOCKS (NROWS / ROWS_PER_BLOCK)   // 4096

__device__ float g_partials[NBLOCKS];

__global__ void __launch_bounds__(256, 8)
hloss_main(const float* __restrict__ outputs, const int* __restrict__ target) {
    const int warp = threadIdx.x >> 5;
    const int lane = threadIdx.x & 31;
    const int row  = blockIdx.x * ROWS_PER_BLOCK + warp;

    const float4* __restrict__ rowp =
        reinterpret_cast<const float4*>(outputs + (size_t)row * NCOLS);
    const int t = target[row];
    const int g100lo = (t / 100) * 100;
    const int g10lo  = (t / 10)  * 10;

    float s_all = 0.f, s100 = 0.f, s10 = 0.f, xt = 0.f;

    // 7 full iterations: all 32 lanes load (indices 0..223)
    float4 v[7];
#pragma unroll
    for (int i = 0; i < 7; ++i)
        v[i] = rowp[lane + i * 32];          // batched -> high MLP

#pragma unroll
    for (int i = 0; i < 7; ++i) {
        const int j = (lane + i * 32) * 4;
        const float vals[4] = {v[i].x, v[i].y, v[i].z, v[i].w};
#pragma unroll
        for (int k = 0; k < 4; ++k) {
            const float x = vals[k];
            const int jj = j + k;
            s_all += x;
            s100 += ((unsigned)(jj - g100lo) < 100u) ? x : 0.f;
            s10  += ((unsigned)(jj - g10lo)  < 10u)  ? x : 0.f;
            xt   += (jj == t) ? x : 0.f;
        }
    }
    // tail: float4 indices 224..249 (lanes 0..25)
    if (lane < (F4_PER_ROW - 224)) {
        const int f4 = 224 + lane;
        const float4 vt = rowp[f4];
        const int j = f4 * 4;
        const float vals[4] = {vt.x, vt.y, vt.z, vt.w};
#pragma unroll
        for (int k = 0; k < 4; ++k) {
            const float x = vals[k];
            const int jj = j + k;
            s_all += x;
            s100 += ((unsigned)(jj - g100lo) < 100u) ? x : 0.f;
            s10  += ((unsigned)(jj - g10lo)  < 10u)  ? x : 0.f;
            xt   += (jj == t) ? x : 0.f;
        }
    }

    float win = 0.5f * s_all + 0.25f * s100 + 0.125f * s10 + 0.125f * xt;
#pragma unroll
    for (int off = 16; off; off >>= 1)
        win += __shfl_xor_sync(0xffffffffu, win, off);

    __shared__ float ssum[ROWS_PER_BLOCK];
    if (lane == 0) ssum[warp] = 1.0f - win;
    __syncthreads();
    if (threadIdx.x == 0) {
        float acc = 0.f;
#pragma unroll
        for (int w = 0; w < ROWS_PER_BLOCK; ++w) acc += ssum[w];
        g_partials[blockIdx.x] = acc;
    }
}

__global__ void __launch_bounds__(1024)
hloss_final(float* __restrict__ out) {
    __shared__ float s[1024];
    float a = 0.f;
#pragma unroll
    for (int i = 0; i < NBLOCKS / 1024; ++i)
        a += g_partials[threadIdx.x + i * 1024];
    s[threadIdx.x] = a;
    __syncthreads();
#pragma unroll
    for (int stride = 512; stride >= 1; stride >>= 1) {
        if (threadIdx.x < stride) s[threadIdx.x] += s[threadIdx.x + stride];
        __syncthreads();
    }
    if (threadIdx.x == 0) out[0] = s[0];
}

extern "C" void kernel_launch(void* const* d_in, const int* in_sizes, int n_in,
                              void* d_out, int out_size) {
    const float* outputs = (const float*)d_in[0];   // [32768, 1000] f32
    const int*   target  = (const int*)d_in[1];     // [32768] i32
    float* out = (float*)d_out;                     // scalar f32

    hloss_main<<<NBLOCKS, 256>>>(outputs, target);
    hloss_final<<<1, 1024>>>(out);
}

// round 2
// speedup vs baseline: 1.0762x; 1.0762x over previous
#include <cuda_runtime.h>

// Heirachical_Loss: loss = sum_i (1 - win_i)
// win_i = 0.5*S_all(i) + 0.25*S100(i) + 0.125*S10(i) + 0.125*x[i,t]
// where S100/S10 are sums over the 100-/10-aligned group containing t.
// B=32768 rows, C=1000 classes, fp32. HBM-streaming bound.
//
// Main loop computes ONLY S_all (packed f32x2 adds). The 111-element subset
// (100-group ⊇ 10-group ∋ t) is re-read in a tiny second pass (L1/L2 hot).
// Single fused kernel: last block does the deterministic final reduction.

#define NROWS 32768
#define NCOLS 1000
#define ROWS_PER_BLOCK 8
#define NBLOCKS (NROWS / ROWS_PER_BLOCK)   // 4096
#define BLOCK_THREADS 256

__device__ float g_partials[NBLOCKS];
__device__ unsigned int g_count;           // zero-init; reset by last block each call

#define ADD_F32X2(acc, v) \
    asm("add.rn.f32x2 %0, %0, %1;" : "+l"(acc) : "l"(v))

__global__ void __launch_bounds__(BLOCK_THREADS, 8)
hloss_fused(const float* __restrict__ outputs, const int* __restrict__ target,
            float* __restrict__ out) {
    const int warp = threadIdx.x >> 5;
    const int lane = threadIdx.x & 31;
    const int row  = blockIdx.x * ROWS_PER_BLOCK + warp;

    const float* __restrict__ rowf = outputs + (size_t)row * NCOLS;
    const ulonglong2* __restrict__ rowp = reinterpret_cast<const ulonglong2*>(rowf);

    const int t = target[row];
    const int g100lo = (t / 100) * 100;     // multiple of 100 (divisible by 4)
    const int g10lo  = (t / 10)  * 10;

    // ---- Pass 1: S_all via packed f32x2 adds (memory-bound stream) ----
    unsigned long long a0 = 0ull, a1 = 0ull;   // two packed f32x2 accumulators
    {
        ulonglong2 v[7];
#pragma unroll
        for (int i = 0; i < 7; ++i)
            v[i] = rowp[lane + i * 32];        // batched 16B loads, high MLP
#pragma unroll
        for (int i = 0; i < 7; ++i) {
            ADD_F32X2(a0, v[i].x);
            ADD_F32X2(a1, v[i].y);
        }
        if (lane < 26) {                        // float4 indices 224..249
            ulonglong2 vt = rowp[224 + lane];
            ADD_F32X2(a0, vt.x);
            ADD_F32X2(a1, vt.y);
        }
    }
    float s_all;
    {
        float r0, r1, r2, r3;
        asm("mov.b64 {%0, %1}, %2;" : "=f"(r0), "=f"(r1) : "l"(a0));
        asm("mov.b64 {%0, %1}, %2;" : "=f"(r2), "=f"(r3) : "l"(a1));
        s_all = (r0 + r1) + (r2 + r3);
    }

    // ---- Pass 2: 100-group subset (25 float4s, lanes 0..24; L1/L2 hot) ----
    float s100 = 0.f, s10 = 0.f, xt = 0.f;
    if (lane < 25) {
        const float4 v = reinterpret_cast<const float4*>(rowf + g100lo)[lane];
        const int j = g100lo + lane * 4;
        const float vals[4] = {v.x, v.y, v.z, v.w};
#pragma unroll
        for (int k = 0; k < 4; ++k) {
            const float x = vals[k];
            const int jj = j + k;
            s100 += x;
            s10  += ((unsigned)(jj - g10lo) < 10u) ? x : 0.f;
            xt   += (jj == t) ? x : 0.f;
        }
    }

    float win = 0.5f * s_all + 0.25f * s100 + 0.125f * (s10 + xt);
#pragma unroll
    for (int off = 16; off; off >>= 1)
        win += __shfl_xor_sync(0xffffffffu, win, off);

    __shared__ float ssum[ROWS_PER_BLOCK];
    __shared__ bool is_last;
    if (lane == 0) ssum[warp] = 1.0f - win;
    __syncthreads();

    if (threadIdx.x == 0) {
        float acc = 0.f;
#pragma unroll
        for (int w = 0; w < ROWS_PER_BLOCK; ++w) acc += ssum[w];
        g_partials[blockIdx.x] = acc;
        __threadfence();
        unsigned int old = atomicAdd(&g_count, 1u);
        is_last = (old == (unsigned)(NBLOCKS - 1));
    }
    __syncthreads();

    // ---- Last block: deterministic fixed-order final reduction ----
    if (is_last) {
        __shared__ float fs[BLOCK_THREADS];
        float a = 0.f;
#pragma unroll
        for (int i = 0; i < NBLOCKS / BLOCK_THREADS; ++i)     // 16 each, fixed order
            a += g_partials[threadIdx.x + i * BLOCK_THREADS];
        fs[threadIdx.x] = a;
        __syncthreads();
#pragma unroll
        for (int stride = BLOCK_THREADS / 2; stride >= 1; stride >>= 1) {
            if (threadIdx.x < stride) fs[threadIdx.x] += fs[threadIdx.x + stride];
            __syncthreads();
        }
        if (threadIdx.x == 0) {
            out[0] = fs[0];
            g_count = 0u;          // reset for next graph replay
        }
    }
}

extern "C" void kernel_launch(void* const* d_in, const int* in_sizes, int n_in,
                              void* d_out, int out_size) {
    const float* outputs = (const float*)d_in[0];   // [32768, 1000] f32
    const int*   target  = (const int*)d_in[1];     // [32768] i32
    float* out = (float*)d_out;                     // scalar f32

    hloss_fused<<<NBLOCKS, BLOCK_THREADS>>>(outputs, target, out);
}